// round 1
// baseline (speedup 1.0000x reference)
#include <cuda_runtime.h>

// Problem constants
#define BB    4
#define SS    1024
#define HIDD  2048
#define HH    16
#define DD    128
#define CACHE 2048
#define LTOT  (CACHE + SS)   // 3072
#define MM    (BB * SS)      // 4096

// Scratch (device globals: allocation-guard safe)
__device__ float g_q[MM * HIDD];     // [B,H,S,D]
__device__ float g_k[MM * HIDD];     // [B,H,S,D] (new K)
__device__ float g_v[MM * HIDD];     // [B,H,S,D] (new V)
__device__ float g_attn[MM * HIDD];  // [B,S,H,D] == [M, HID]

// ---------------------------------------------------------------------------
// Fast exp on the FMA pipe (avoids MUFU.EX2 throughput wall: 201M exps).
// exp(x) = 2^(x*log2e); round-trick + degree-5 poly on [-0.5,0.5]; ~2e-6 rel.
// ---------------------------------------------------------------------------
__device__ __forceinline__ float fast_exp(float x) {
    float t = x * 1.4426950408889634f;
    t = fmaxf(t, -125.0f);
    float r = __fadd_rn(t, 12582912.0f);              // 1.5*2^23: round-to-int
    float f = __fsub_rn(t, __fsub_rn(r, 12582912.0f)); // frac in [-0.5, 0.5]
    float p = 1.3333558e-3f;
    p = fmaf(p, f, 9.6181291e-3f);
    p = fmaf(p, f, 5.5504109e-2f);
    p = fmaf(p, f, 2.4022651e-1f);
    p = fmaf(p, f, 6.9314718e-1f);
    p = fmaf(p, f, 1.0f);
    int n = __float_as_int(r) - 0x4B400000;            // integer part
    return p * __int_as_float((n + 127) << 23);        // * 2^n
}

// ---------------------------------------------------------------------------
// Kernel 1: QKV GEMM.  C[m,n] = sum_k x[m,k] * w_qkv[n,k] + b_qkv[n]
// 128x128x16 tiles, 256 threads, 8x8 micro-tile (2x2 quadrants of 4).
// Epilogue scatters into g_q / g_k / g_v with [B,H,S,D] layout.
// ---------------------------------------------------------------------------
__global__ __launch_bounds__(256) void k_qkv(
    const float* __restrict__ x, const float* __restrict__ w,
    const float* __restrict__ bias)
{
    __shared__ float As[16][128];   // A transposed: As[k][m]
    __shared__ float Bs[16][128];   // B transposed: Bs[k][n]

    const int tid = threadIdx.x;
    const int tx = tid & 15;
    const int ty = tid >> 4;
    const int m0 = blockIdx.y * 128;
    const int n0 = blockIdx.x * 128;

    float acc[8][8];
#pragma unroll
    for (int i = 0; i < 8; i++)
#pragma unroll
        for (int j = 0; j < 8; j++) acc[i][j] = 0.f;

    for (int kt = 0; kt < HIDD; kt += 16) {
        __syncthreads();
#pragma unroll
        for (int r = 0; r < 2; r++) {
            int idx = tid * 2 + r;           // 0..511 float4 slots
            int row = idx >> 2;              // 0..127
            int cq  = (idx & 3) << 2;        // 0,4,8,12
            float4 av = *(const float4*)(x + (m0 + row) * HIDD + kt + cq);
            As[cq + 0][row] = av.x; As[cq + 1][row] = av.y;
            As[cq + 2][row] = av.z; As[cq + 3][row] = av.w;
            float4 bv = *(const float4*)(w + (n0 + row) * HIDD + kt + cq);
            Bs[cq + 0][row] = bv.x; Bs[cq + 1][row] = bv.y;
            Bs[cq + 2][row] = bv.z; Bs[cq + 3][row] = bv.w;
        }
        __syncthreads();
#pragma unroll
        for (int k = 0; k < 16; k++) {
            float4 a0 = *(const float4*)&As[k][ty * 4];
            float4 a1 = *(const float4*)&As[k][ty * 4 + 64];
            float4 b0 = *(const float4*)&Bs[k][tx * 4];
            float4 b1 = *(const float4*)&Bs[k][tx * 4 + 64];
            float af[8] = {a0.x, a0.y, a0.z, a0.w, a1.x, a1.y, a1.z, a1.w};
            float bf[8] = {b0.x, b0.y, b0.z, b0.w, b1.x, b1.y, b1.z, b1.w};
#pragma unroll
            for (int i = 0; i < 8; i++)
#pragma unroll
                for (int j = 0; j < 8; j++)
                    acc[i][j] = fmaf(af[i], bf[j], acc[i][j]);
        }
    }

    // Epilogue: a 128-wide aligned N tile covers exactly one (which, h), d=col
    const int which = blockIdx.x >> 4;       // 0:q 1:k 2:v
    const int h = blockIdx.x & 15;
    float* dst = (which == 0) ? g_q : ((which == 1) ? g_k : g_v);

    float bvv[8];
#pragma unroll
    for (int jq = 0; jq < 2; jq++)
#pragma unroll
        for (int j = 0; j < 4; j++)
            bvv[jq * 4 + j] = bias[n0 + jq * 64 + tx * 4 + j];

#pragma unroll
    for (int iq = 0; iq < 2; iq++)
#pragma unroll
        for (int i = 0; i < 4; i++) {
            int m = m0 + iq * 64 + ty * 4 + i;
            int b = m >> 10, s = m & 1023;
            float* drow = dst + (((b * HH + h) << 10) + s) * DD;
#pragma unroll
            for (int jq = 0; jq < 2; jq++) {
                float4 v;
                v.x = acc[iq * 4 + i][jq * 4 + 0] + bvv[jq * 4 + 0];
                v.y = acc[iq * 4 + i][jq * 4 + 1] + bvv[jq * 4 + 1];
                v.z = acc[iq * 4 + i][jq * 4 + 2] + bvv[jq * 4 + 2];
                v.w = acc[iq * 4 + i][jq * 4 + 3] + bvv[jq * 4 + 3];
                *(float4*)(drow + jq * 64 + tx * 4) = v;
            }
        }
}

// ---------------------------------------------------------------------------
// Kernel 2: flash attention, fp32, online softmax.
// Grid: (S/64, B*H). Block: 256 threads. BQ=64, BKV=64, full D=128.
// smem: Qs^T[128][64] Ks^T[128][64] Vs[64][128] Ps[64][68]  = 113 KB dynamic.
// ---------------------------------------------------------------------------
__global__ __launch_bounds__(256) void k_attn(
    const float* __restrict__ ck, const float* __restrict__ cv)
{
    extern __shared__ float sm[];
    float* Qs = sm;              // [128][64]  Qs[d][q]  (pre-scaled)
    float* Ks = sm + 8192;       // [128][64]  Ks[d][kv]
    float* Vs = sm + 16384;      // [64][128]  Vs[kv][d]
    float* Ps = sm + 24576;      // [64][68]   Ps[q][kv]  (pad 68 vs bank)

    const int tid = threadIdx.x;
    const int tx = tid & 15;
    const int ty = tid >> 4;
    const int bh = blockIdx.y;            // b*16 + h
    const int b = bh >> 4, h = bh & 15;
    const int q0 = blockIdx.x * 64;
    const float scale = 0.08838834764831845f;  // 1/sqrt(128)

    // row-per-lane mapping: conflict-free transposed smem stores
    const int lrow = tid & 63;            // 0..63
    const int lc8  = tid >> 6;            // 0..3 (8 float4s each)

    // ---- load Q tile (scaled) into Qs^T ----
    const float* qbase = g_q + (bh * SS + q0) * DD;
#pragma unroll
    for (int i = 0; i < 8; i++) {
        int d4 = (lc8 * 8 + i) << 2;
        float4 v = *(const float4*)(qbase + lrow * DD + d4);
        Qs[(d4 + 0) * 64 + lrow] = v.x * scale;
        Qs[(d4 + 1) * 64 + lrow] = v.y * scale;
        Qs[(d4 + 2) * 64 + lrow] = v.z * scale;
        Qs[(d4 + 3) * 64 + lrow] = v.w * scale;
    }

    const float* knew = g_k + bh * (SS * DD);
    const float* vnew = g_v + bh * (SS * DD);
    const float* kcache = ck + h * DD;    // cached_k[(t*H+h)*D]
    const float* vcache = cv + h * DD;

    float m_i[4], l_i[4], o[4][8];
#pragma unroll
    for (int i = 0; i < 4; i++) {
        m_i[i] = -1e30f; l_i[i] = 0.f;
#pragma unroll
        for (int c = 0; c < 8; c++) o[i][c] = 0.f;
    }

    for (int t = 0; t < LTOT / 64; t++) {
        const int kv0 = t * 64;
        __syncthreads();   // protect Ks/Vs/Ps from previous iteration readers

        // ---- load K (transposed, row-per-lane) and V (natural, coalesced) ----
        {
            int kv = kv0 + lrow;
            const float* ksrc = (kv < CACHE) ? (kcache + kv * (HH * DD))
                                             : (knew + (kv - CACHE) * DD);
#pragma unroll
            for (int i = 0; i < 8; i++) {
                int d4 = (lc8 * 8 + i) << 2;
                float4 v = *(const float4*)(ksrc + d4);
                Ks[(d4 + 0) * 64 + lrow] = v.x;
                Ks[(d4 + 1) * 64 + lrow] = v.y;
                Ks[(d4 + 2) * 64 + lrow] = v.z;
                Ks[(d4 + 3) * 64 + lrow] = v.w;
            }
#pragma unroll
            for (int i = 0; i < 8; i++) {
                int idx = tid + (i << 8);      // 0..2047 float4 slots
                int row = idx >> 5;
                int d4 = (idx & 31) << 2;
                int kvv = kv0 + row;
                const float* vsrc = (kvv < CACHE)
                    ? (vcache + kvv * (HH * DD) + d4)
                    : (vnew + (kvv - CACHE) * DD + d4);
                *(float4*)&Vs[row * DD + d4] = *(const float4*)vsrc;
            }
        }
        __syncthreads();

        // ---- scores: s[4][4] = Q(64x128) @ K^T(128x64) micro 4x4 ----
        float s[4][4];
#pragma unroll
        for (int i = 0; i < 4; i++)
#pragma unroll
            for (int j = 0; j < 4; j++) s[i][j] = 0.f;
#pragma unroll 8
        for (int k = 0; k < 128; k++) {
            float4 qv = *(const float4*)&Qs[k * 64 + ty * 4];
            float4 kv4 = *(const float4*)&Ks[k * 64 + tx * 4];
            float qa[4] = {qv.x, qv.y, qv.z, qv.w};
            float ka[4] = {kv4.x, kv4.y, kv4.z, kv4.w};
#pragma unroll
            for (int i = 0; i < 4; i++)
#pragma unroll
                for (int j = 0; j < 4; j++)
                    s[i][j] = fmaf(qa[i], ka[j], s[i][j]);
        }

        // ---- online softmax (row spread over 16 tx lanes = half-warp) ----
#pragma unroll
        for (int i = 0; i < 4; i++) {
            float mx = fmaxf(fmaxf(s[i][0], s[i][1]), fmaxf(s[i][2], s[i][3]));
#pragma unroll
            for (int off = 8; off > 0; off >>= 1)
                mx = fmaxf(mx, __shfl_xor_sync(0xffffffffu, mx, off));
            float mnew = fmaxf(m_i[i], mx);
            float alpha = fast_exp(m_i[i] - mnew);
            m_i[i] = mnew;
            float ps = 0.f;
#pragma unroll
            for (int j = 0; j < 4; j++) {
                float p = fast_exp(s[i][j] - mnew);
                s[i][j] = p;
                ps += p;
            }
#pragma unroll
            for (int off = 8; off > 0; off >>= 1)
                ps += __shfl_xor_sync(0xffffffffu, ps, off);
            l_i[i] = l_i[i] * alpha + ps;
#pragma unroll
            for (int c = 0; c < 8; c++) o[i][c] *= alpha;
            Ps[(ty * 4 + i) * 68 + tx * 4 + 0] = s[i][0];
            Ps[(ty * 4 + i) * 68 + tx * 4 + 1] = s[i][1];
            Ps[(ty * 4 + i) * 68 + tx * 4 + 2] = s[i][2];
            Ps[(ty * 4 + i) * 68 + tx * 4 + 3] = s[i][3];
        }
        __syncthreads();

        // ---- PV: O(64x128) += P(64x64) @ V(64x128), micro 4x8 ----
#pragma unroll 4
        for (int kj = 0; kj < 64; kj++) {
            float4 v0 = *(const float4*)&Vs[kj * DD + tx * 4];
            float4 v1 = *(const float4*)&Vs[kj * DD + 64 + tx * 4];
#pragma unroll
            for (int i = 0; i < 4; i++) {
                float p = Ps[(ty * 4 + i) * 68 + kj];
                o[i][0] = fmaf(p, v0.x, o[i][0]);
                o[i][1] = fmaf(p, v0.y, o[i][1]);
                o[i][2] = fmaf(p, v0.z, o[i][2]);
                o[i][3] = fmaf(p, v0.w, o[i][3]);
                o[i][4] = fmaf(p, v1.x, o[i][4]);
                o[i][5] = fmaf(p, v1.y, o[i][5]);
                o[i][6] = fmaf(p, v1.z, o[i][6]);
                o[i][7] = fmaf(p, v1.w, o[i][7]);
            }
        }
    }

    // ---- epilogue: normalize and write [B,S,H,D] ----
#pragma unroll
    for (int i = 0; i < 4; i++) {
        int m = b * SS + q0 + ty * 4 + i;
        float inv = __fdividef(1.0f, l_i[i]);
        float* orow = g_attn + m * HIDD + h * DD;
        float4 w0 = {o[i][0] * inv, o[i][1] * inv, o[i][2] * inv, o[i][3] * inv};
        float4 w1 = {o[i][4] * inv, o[i][5] * inv, o[i][6] * inv, o[i][7] * inv};
        *(float4*)(orow + tx * 4) = w0;
        *(float4*)(orow + 64 + tx * 4) = w1;
    }
}

// ---------------------------------------------------------------------------
// Kernel 3: output projection.  out[m,n] = sum_k attn[m,k] * w_proj[n,k] + b[n]
// ---------------------------------------------------------------------------
__global__ __launch_bounds__(256) void k_proj(
    const float* __restrict__ w, const float* __restrict__ bias,
    float* __restrict__ out)
{
    __shared__ float As[16][128];
    __shared__ float Bs[16][128];

    const int tid = threadIdx.x;
    const int tx = tid & 15;
    const int ty = tid >> 4;
    const int m0 = blockIdx.y * 128;
    const int n0 = blockIdx.x * 128;

    float acc[8][8];
#pragma unroll
    for (int i = 0; i < 8; i++)
#pragma unroll
        for (int j = 0; j < 8; j++) acc[i][j] = 0.f;

    for (int kt = 0; kt < HIDD; kt += 16) {
        __syncthreads();
#pragma unroll
        for (int r = 0; r < 2; r++) {
            int idx = tid * 2 + r;
            int row = idx >> 2;
            int cq  = (idx & 3) << 2;
            float4 av = *(const float4*)(g_attn + (m0 + row) * HIDD + kt + cq);
            As[cq + 0][row] = av.x; As[cq + 1][row] = av.y;
            As[cq + 2][row] = av.z; As[cq + 3][row] = av.w;
            float4 bv = *(const float4*)(w + (n0 + row) * HIDD + kt + cq);
            Bs[cq + 0][row] = bv.x; Bs[cq + 1][row] = bv.y;
            Bs[cq + 2][row] = bv.z; Bs[cq + 3][row] = bv.w;
        }
        __syncthreads();
#pragma unroll
        for (int k = 0; k < 16; k++) {
            float4 a0 = *(const float4*)&As[k][ty * 4];
            float4 a1 = *(const float4*)&As[k][ty * 4 + 64];
            float4 b0 = *(const float4*)&Bs[k][tx * 4];
            float4 b1 = *(const float4*)&Bs[k][tx * 4 + 64];
            float af[8] = {a0.x, a0.y, a0.z, a0.w, a1.x, a1.y, a1.z, a1.w};
            float bf[8] = {b0.x, b0.y, b0.z, b0.w, b1.x, b1.y, b1.z, b1.w};
#pragma unroll
            for (int i = 0; i < 8; i++)
#pragma unroll
                for (int j = 0; j < 8; j++)
                    acc[i][j] = fmaf(af[i], bf[j], acc[i][j]);
        }
    }

    float bvv[8];
#pragma unroll
    for (int jq = 0; jq < 2; jq++)
#pragma unroll
        for (int j = 0; j < 4; j++)
            bvv[jq * 4 + j] = bias[n0 + jq * 64 + tx * 4 + j];

#pragma unroll
    for (int iq = 0; iq < 2; iq++)
#pragma unroll
        for (int i = 0; i < 4; i++) {
            int m = m0 + iq * 64 + ty * 4 + i;
            float* drow = out + m * HIDD + n0;
#pragma unroll
            for (int jq = 0; jq < 2; jq++) {
                float4 v;
                v.x = acc[iq * 4 + i][jq * 4 + 0] + bvv[jq * 4 + 0];
                v.y = acc[iq * 4 + i][jq * 4 + 1] + bvv[jq * 4 + 1];
                v.z = acc[iq * 4 + i][jq * 4 + 2] + bvv[jq * 4 + 2];
                v.w = acc[iq * 4 + i][jq * 4 + 3] + bvv[jq * 4 + 3];
                *(float4*)(drow + jq * 64 + tx * 4) = v;
            }
        }
}

// ---------------------------------------------------------------------------
extern "C" void kernel_launch(void* const* d_in, const int* in_sizes, int n_in,
                              void* d_out, int out_size) {
    const float* x     = (const float*)d_in[0];
    const float* ck    = (const float*)d_in[1];
    const float* cv    = (const float*)d_in[2];
    const float* wqkv  = (const float*)d_in[3];
    const float* bqkv  = (const float*)d_in[4];
    const float* wproj = (const float*)d_in[5];
    const float* bproj = (const float*)d_in[6];
    float* out = (float*)d_out;

    // K1: QKV projection -> g_q/g_k/g_v in [B,H,S,D]
    k_qkv<<<dim3(3 * HIDD / 128, MM / 128), 256>>>(x, wqkv, bqkv);

    // K2: flash attention -> g_attn in [B,S,H,D]
    const int smem_attn = (8192 + 8192 + 8192 + 64 * 68) * (int)sizeof(float);
    cudaFuncSetAttribute(k_attn, cudaFuncAttributeMaxDynamicSharedMemorySize,
                         smem_attn);
    k_attn<<<dim3(SS / 64, BB * HH), 256, smem_attn>>>(ck, cv);

    // K3: output projection -> d_out
    k_proj<<<dim3(HIDD / 128, MM / 128), 256>>>(wproj, bproj, out);
}

// round 4
// speedup vs baseline: 1.3852x; 1.3852x over previous
#include <cuda_runtime.h>
#include <cuda_bf16.h>
#include <cstdint>

// Problem constants
#define BB    4
#define SS    1024
#define HIDD  2048
#define HH    16
#define DD    128
#define CACHE 2048
#define LTOT  (CACHE + SS)   // 3072
#define MM    (BB * SS)      // 4096

// ---------------------------------------------------------------------------
// Scratch (device globals: allocation-guard safe)
// ---------------------------------------------------------------------------
__device__ float g_q[MM * HIDD];     // [B,H,S,D]
__device__ float g_k[MM * HIDD];     // [B,H,S,D] (new K)
__device__ float g_v[MM * HIDD];     // [B,H,S,D] (new V)
__device__ float g_attn[MM * HIDD];  // [B,S,H,D] == [M, HID]

// bf16 hi/lo splits for tensor-core GEMMs
__device__ __align__(16) __nv_bfloat16 g_xh[MM * HIDD],        g_xl[MM * HIDD];
__device__ __align__(16) __nv_bfloat16 g_wqh[3 * HIDD * HIDD], g_wql[3 * HIDD * HIDD];
__device__ __align__(16) __nv_bfloat16 g_wph[HIDD * HIDD],     g_wpl[HIDD * HIDD];
__device__ __align__(16) __nv_bfloat16 g_ah[MM * HIDD],        g_al[MM * HIDD];

// ---------------------------------------------------------------------------
// Helpers (compute_103-safe: mma.sync / ldmatrix / cp.async only)
// ---------------------------------------------------------------------------
__device__ __forceinline__ uint32_t smem_u32(const void* p) {
    return (uint32_t)__cvta_generic_to_shared(p);
}

__device__ __forceinline__ void ldsm4(uint32_t* r, uint32_t addr) {
    asm volatile("ldmatrix.sync.aligned.m8n8.x4.shared.b16 {%0,%1,%2,%3}, [%4];"
                 : "=r"(r[0]), "=r"(r[1]), "=r"(r[2]), "=r"(r[3]) : "r"(addr));
}

__device__ __forceinline__ void mma16816(float* c, const uint32_t* a,
                                         const uint32_t* b) {
    asm volatile(
        "mma.sync.aligned.m16n8k16.row.col.f32.bf16.bf16.f32 "
        "{%0,%1,%2,%3}, {%4,%5,%6,%7}, {%8,%9}, {%0,%1,%2,%3};"
        : "+f"(c[0]), "+f"(c[1]), "+f"(c[2]), "+f"(c[3])
        : "r"(a[0]), "r"(a[1]), "r"(a[2]), "r"(a[3]), "r"(b[0]), "r"(b[1]));
}

__device__ __forceinline__ void cp16(uint32_t dst, const void* src) {
    asm volatile("cp.async.cg.shared.global [%0], [%1], 16;"
                 :: "r"(dst), "l"(src) : "memory");
}
#define CP_COMMIT() asm volatile("cp.async.commit_group;" ::: "memory")
#define CP_WAIT1()  asm volatile("cp.async.wait_group 1;" ::: "memory")

// ---------------------------------------------------------------------------
// Split fp32 -> bf16 hi + bf16 lo (exact residual in fp32)
// ---------------------------------------------------------------------------
template <int WHICH>
__global__ __launch_bounds__(256) void k_split(const float* __restrict__ in, int n4) {
    int i = blockIdx.x * 256 + threadIdx.x;
    if (i >= n4) return;
    const float4* src;
    __nv_bfloat162* dh;
    __nv_bfloat162* dl;
    if (WHICH == 0) { src = (const float4*)in;     dh = (__nv_bfloat162*)g_xh; dl = (__nv_bfloat162*)g_xl; }
    if (WHICH == 1) { src = (const float4*)in;     dh = (__nv_bfloat162*)g_wqh; dl = (__nv_bfloat162*)g_wql; }
    if (WHICH == 2) { src = (const float4*)in;     dh = (__nv_bfloat162*)g_wph; dl = (__nv_bfloat162*)g_wpl; }
    if (WHICH == 3) { src = (const float4*)g_attn; dh = (__nv_bfloat162*)g_ah; dl = (__nv_bfloat162*)g_al; }
    float4 v = src[i];
    __nv_bfloat16 h0 = __float2bfloat16(v.x), h1 = __float2bfloat16(v.y);
    __nv_bfloat16 h2 = __float2bfloat16(v.z), h3 = __float2bfloat16(v.w);
    __nv_bfloat16 l0 = __float2bfloat16(v.x - __bfloat162float(h0));
    __nv_bfloat16 l1 = __float2bfloat16(v.y - __bfloat162float(h1));
    __nv_bfloat16 l2 = __float2bfloat16(v.z - __bfloat162float(h2));
    __nv_bfloat16 l3 = __float2bfloat16(v.w - __bfloat162float(h3));
    __nv_bfloat162 a, b, c, d;
    a.x = h0; a.y = h1;  b.x = h2; b.y = h3;
    c.x = l0; c.y = l1;  d.x = l2; d.y = l3;
    dh[2 * i] = a; dh[2 * i + 1] = b;
    dl[2 * i] = c; dl[2 * i + 1] = d;
}

// ---------------------------------------------------------------------------
// mma.sync bf16 split-fp32 GEMM:  C[m,n] = sum_k A[m,k]*B[n,k] + bias[n]
// Tile 128x128, KC=32, 3-stage cp.async pipeline, 8 warps (2m x 4n), warp
// tile 64x32. Smem rows padded to 80B (conflict-free ldmatrix, no xor).
// MODE 1: A=g_xh/l, B=g_wqh/l [6144,2048] -> scatter to g_q/g_k/g_v
// MODE 0: A=g_ah/l, B=g_wph/l [2048,2048] -> out
// ---------------------------------------------------------------------------
#define TILEB  (128 * 80)          // 10240 bytes per bf16 tile
#define STG    (4 * TILEB)         // Ah, Al, Bh, Bl
#define NIT    (HIDD / 32)         // 64

template <int MODE>
__global__ __launch_bounds__(256) void k_gemm_mma(const float* __restrict__ bias,
                                                  float* __restrict__ out)
{
    extern __shared__ __align__(128) char smem[];   // 3 * STG

    const __nv_bfloat16* __restrict__ Ah = MODE ? g_xh : g_ah;
    const __nv_bfloat16* __restrict__ Al = MODE ? g_xl : g_al;
    const __nv_bfloat16* __restrict__ Bh = MODE ? g_wqh : g_wph;
    const __nv_bfloat16* __restrict__ Bl = MODE ? g_wql : g_wpl;

    const int tid = threadIdx.x;
    const int wid = tid >> 5, lane = tid & 31;
    const int m0 = blockIdx.y * 128;
    const int n0 = blockIdx.x * 128;
    const int warp_m = wid & 1;        // 0,1  -> 64-row halves
    const int warp_n = wid >> 1;       // 0..3 -> 32-col quarters

    // ---- loader mapping: 512 16B chunks per tile, 2 per thread per tile ----
    const int lr = tid >> 2;           // 0..63
    const int lc = tid & 3;            // 0..3 (16B column)
    const size_t aoff0 = (size_t)(m0 + lr) * HIDD + lc * 8;
    const size_t aoff1 = (size_t)(m0 + 64 + lr) * HIDD + lc * 8;
    const size_t boff0 = (size_t)(n0 + lr) * HIDD + lc * 8;
    const size_t boff1 = (size_t)(n0 + 64 + lr) * HIDD + lc * 8;
    const int dst0 = lr * 80 + lc * 16;
    const int dst1 = (64 + lr) * 80 + lc * 16;

    auto issue = [&](int t, int slot) {
        const int kc = t * 32;
        char* sb = smem + slot * STG;
        uint32_t s0 = smem_u32(sb);
        cp16(s0 + 0 * TILEB + dst0, Ah + aoff0 + kc);
        cp16(s0 + 0 * TILEB + dst1, Ah + aoff1 + kc);
        cp16(s0 + 1 * TILEB + dst0, Al + aoff0 + kc);
        cp16(s0 + 1 * TILEB + dst1, Al + aoff1 + kc);
        cp16(s0 + 2 * TILEB + dst0, Bh + boff0 + kc);
        cp16(s0 + 2 * TILEB + dst1, Bh + boff1 + kc);
        cp16(s0 + 3 * TILEB + dst0, Bl + boff0 + kc);
        cp16(s0 + 3 * TILEB + dst1, Bl + boff1 + kc);
        CP_COMMIT();
    };

    // ---- ldmatrix per-thread address components ----
    const int arow_l = (lane & 7) + ((lane >> 3) & 1) * 8;  // A: m within frag
    const int ac16   = lane >> 4;                           // A: 16B col sel
    const int brow_l = (lane & 7) + (lane >> 4) * 8;        // B: n within frag
    const int bc16   = (lane >> 3) & 1;                     // B: 16B col sel

    float acc[4][4][4];
#pragma unroll
    for (int mf = 0; mf < 4; mf++)
#pragma unroll
        for (int nf = 0; nf < 4; nf++)
#pragma unroll
            for (int c = 0; c < 4; c++) acc[mf][nf][c] = 0.f;

    issue(0, 0);
    issue(1, 1);

    for (int t = 0; t < NIT; t++) {
        CP_WAIT1();
        __syncthreads();
        if (t + 2 < NIT) issue(t + 2, (t + 2) % 3);

        const uint32_t sb = smem_u32(smem + (t % 3) * STG);
        const uint32_t sAh = sb;
        const uint32_t sAl = sb + TILEB;
        const uint32_t sBh = sb + 2 * TILEB;
        const uint32_t sBl = sb + 3 * TILEB;

#pragma unroll
        for (int kk = 0; kk < 2; kk++) {
            uint32_t ah[4][4], al[4][4], bh[2][4], bl[2][4];
            const int acol = (kk * 2 + ac16) * 16;
            const int bcol = (kk * 2 + bc16) * 16;
#pragma unroll
            for (int mf = 0; mf < 4; mf++) {
                const int row = warp_m * 64 + mf * 16 + arow_l;
                ldsm4(ah[mf], sAh + row * 80 + acol);
                ldsm4(al[mf], sAl + row * 80 + acol);
            }
#pragma unroll
            for (int nf2 = 0; nf2 < 2; nf2++) {
                const int row = warp_n * 32 + nf2 * 16 + brow_l;
                ldsm4(bh[nf2], sBh + row * 80 + bcol);
                ldsm4(bl[nf2], sBl + row * 80 + bcol);
            }
#pragma unroll
            for (int mf = 0; mf < 4; mf++)
#pragma unroll
                for (int nf = 0; nf < 4; nf++) {
                    const uint32_t* bph = &bh[nf >> 1][(nf & 1) * 2];
                    const uint32_t* bpl = &bl[nf >> 1][(nf & 1) * 2];
                    mma16816(acc[mf][nf], ah[mf], bph);
                    mma16816(acc[mf][nf], ah[mf], bpl);
                    mma16816(acc[mf][nf], al[mf], bph);
                }
        }
    }

    // ---- epilogue ----
#pragma unroll
    for (int mf = 0; mf < 4; mf++) {
#pragma unroll
        for (int nf = 0; nf < 4; nf++) {
            const int gm = m0 + warp_m * 64 + mf * 16 + (lane >> 2);
            const int dn = warp_n * 32 + nf * 8 + (lane & 3) * 2;   // 0..127
            const float b0 = __ldg(bias + n0 + dn);
            const float b1 = __ldg(bias + n0 + dn + 1);
            float* p0;
            if (MODE == 0) {
                p0 = out + (size_t)gm * HIDD + n0 + dn;
            } else {
                const int which = n0 >> 11;          // 0:q 1:k 2:v
                const int h = (n0 >> 7) & 15;
                float* base = (which == 0) ? g_q : ((which == 1) ? g_k : g_v);
                const int bb = gm >> 10, sq = gm & 1023;
                p0 = base + ((((size_t)bb * HH + h) << 10) + sq) * DD + dn;
            }
            float2 v0 = {acc[mf][nf][0] + b0, acc[mf][nf][1] + b1};
            *(float2*)p0 = v0;
            float* p1;
            if (MODE == 0) {
                p1 = p0 + 8 * HIDD;
            } else {
                p1 = p0 + 8 * DD;
            }
            float2 v1 = {acc[mf][nf][2] + b0, acc[mf][nf][3] + b1};
            *(float2*)p1 = v1;
        }
    }
}

// ---------------------------------------------------------------------------
// Fast exp on the FMA pipe (avoids MUFU.EX2 throughput wall).
// ---------------------------------------------------------------------------
__device__ __forceinline__ float fast_exp(float x) {
    float t = x * 1.4426950408889634f;
    t = fmaxf(t, -125.0f);
    float r = __fadd_rn(t, 12582912.0f);
    float f = __fsub_rn(t, __fsub_rn(r, 12582912.0f));
    float p = 1.3333558e-3f;
    p = fmaf(p, f, 9.6181291e-3f);
    p = fmaf(p, f, 5.5504109e-2f);
    p = fmaf(p, f, 2.4022651e-1f);
    p = fmaf(p, f, 6.9314718e-1f);
    p = fmaf(p, f, 1.0f);
    int n = __float_as_int(r) - 0x4B400000;
    return p * __int_as_float((n + 127) << 23);
}

// ---------------------------------------------------------------------------
// Kernel 2: flash attention, fp32, online softmax (unchanged from R1).
// ---------------------------------------------------------------------------
__global__ __launch_bounds__(256) void k_attn(
    const float* __restrict__ ck, const float* __restrict__ cv)
{
    extern __shared__ float sm[];
    float* Qs = sm;              // [128][64]  Qs[d][q]  (pre-scaled)
    float* Ks = sm + 8192;       // [128][64]  Ks[d][kv]
    float* Vs = sm + 16384;      // [64][128]  Vs[kv][d]
    float* Ps = sm + 24576;      // [64][68]

    const int tid = threadIdx.x;
    const int tx = tid & 15;
    const int ty = tid >> 4;
    const int bh = blockIdx.y;
    const int b = bh >> 4, h = bh & 15;
    const int q0 = blockIdx.x * 64;
    const float scale = 0.08838834764831845f;

    const int lrow = tid & 63;
    const int lc8  = tid >> 6;

    const float* qbase = g_q + (bh * SS + q0) * DD;
#pragma unroll
    for (int i = 0; i < 8; i++) {
        int d4 = (lc8 * 8 + i) << 2;
        float4 v = *(const float4*)(qbase + lrow * DD + d4);
        Qs[(d4 + 0) * 64 + lrow] = v.x * scale;
        Qs[(d4 + 1) * 64 + lrow] = v.y * scale;
        Qs[(d4 + 2) * 64 + lrow] = v.z * scale;
        Qs[(d4 + 3) * 64 + lrow] = v.w * scale;
    }

    const float* knew = g_k + bh * (SS * DD);
    const float* vnew = g_v + bh * (SS * DD);
    const float* kcache = ck + h * DD;
    const float* vcache = cv + h * DD;

    float m_i[4], l_i[4], o[4][8];
#pragma unroll
    for (int i = 0; i < 4; i++) {
        m_i[i] = -1e30f; l_i[i] = 0.f;
#pragma unroll
        for (int c = 0; c < 8; c++) o[i][c] = 0.f;
    }

    for (int t = 0; t < LTOT / 64; t++) {
        const int kv0 = t * 64;
        __syncthreads();

        {
            int kv = kv0 + lrow;
            const float* ksrc = (kv < CACHE) ? (kcache + kv * (HH * DD))
                                             : (knew + (kv - CACHE) * DD);
#pragma unroll
            for (int i = 0; i < 8; i++) {
                int d4 = (lc8 * 8 + i) << 2;
                float4 v = *(const float4*)(ksrc + d4);
                Ks[(d4 + 0) * 64 + lrow] = v.x;
                Ks[(d4 + 1) * 64 + lrow] = v.y;
                Ks[(d4 + 2) * 64 + lrow] = v.z;
                Ks[(d4 + 3) * 64 + lrow] = v.w;
            }
#pragma unroll
            for (int i = 0; i < 8; i++) {
                int idx = tid + (i << 8);
                int row = idx >> 5;
                int d4 = (idx & 31) << 2;
                int kvv = kv0 + row;
                const float* vsrc = (kvv < CACHE)
                    ? (vcache + kvv * (HH * DD) + d4)
                    : (vnew + (kvv - CACHE) * DD + d4);
                *(float4*)&Vs[row * DD + d4] = *(const float4*)vsrc;
            }
        }
        __syncthreads();

        float s[4][4];
#pragma unroll
        for (int i = 0; i < 4; i++)
#pragma unroll
            for (int j = 0; j < 4; j++) s[i][j] = 0.f;
#pragma unroll 8
        for (int k = 0; k < 128; k++) {
            float4 qv = *(const float4*)&Qs[k * 64 + ty * 4];
            float4 kv4 = *(const float4*)&Ks[k * 64 + tx * 4];
            float qa[4] = {qv.x, qv.y, qv.z, qv.w};
            float ka[4] = {kv4.x, kv4.y, kv4.z, kv4.w};
#pragma unroll
            for (int i = 0; i < 4; i++)
#pragma unroll
                for (int j = 0; j < 4; j++)
                    s[i][j] = fmaf(qa[i], ka[j], s[i][j]);
        }

#pragma unroll
        for (int i = 0; i < 4; i++) {
            float mx = fmaxf(fmaxf(s[i][0], s[i][1]), fmaxf(s[i][2], s[i][3]));
#pragma unroll
            for (int off = 8; off > 0; off >>= 1)
                mx = fmaxf(mx, __shfl_xor_sync(0xffffffffu, mx, off));
            float mnew = fmaxf(m_i[i], mx);
            float alpha = fast_exp(m_i[i] - mnew);
            m_i[i] = mnew;
            float ps = 0.f;
#pragma unroll
            for (int j = 0; j < 4; j++) {
                float p = fast_exp(s[i][j] - mnew);
                s[i][j] = p;
                ps += p;
            }
#pragma unroll
            for (int off = 8; off > 0; off >>= 1)
                ps += __shfl_xor_sync(0xffffffffu, ps, off);
            l_i[i] = l_i[i] * alpha + ps;
#pragma unroll
            for (int c = 0; c < 8; c++) o[i][c] *= alpha;
            Ps[(ty * 4 + i) * 68 + tx * 4 + 0] = s[i][0];
            Ps[(ty * 4 + i) * 68 + tx * 4 + 1] = s[i][1];
            Ps[(ty * 4 + i) * 68 + tx * 4 + 2] = s[i][2];
            Ps[(ty * 4 + i) * 68 + tx * 4 + 3] = s[i][3];
        }
        __syncthreads();

#pragma unroll 4
        for (int kj = 0; kj < 64; kj++) {
            float4 v0 = *(const float4*)&Vs[kj * DD + tx * 4];
            float4 v1 = *(const float4*)&Vs[kj * DD + 64 + tx * 4];
#pragma unroll
            for (int i = 0; i < 4; i++) {
                float p = Ps[(ty * 4 + i) * 68 + kj];
                o[i][0] = fmaf(p, v0.x, o[i][0]);
                o[i][1] = fmaf(p, v0.y, o[i][1]);
                o[i][2] = fmaf(p, v0.z, o[i][2]);
                o[i][3] = fmaf(p, v0.w, o[i][3]);
                o[i][4] = fmaf(p, v1.x, o[i][4]);
                o[i][5] = fmaf(p, v1.y, o[i][5]);
                o[i][6] = fmaf(p, v1.z, o[i][6]);
                o[i][7] = fmaf(p, v1.w, o[i][7]);
            }
        }
    }

#pragma unroll
    for (int i = 0; i < 4; i++) {
        int m = b * SS + q0 + ty * 4 + i;
        float inv = __fdividef(1.0f, l_i[i]);
        float* orow = g_attn + m * HIDD + h * DD;
        float4 w0 = {o[i][0] * inv, o[i][1] * inv, o[i][2] * inv, o[i][3] * inv};
        float4 w1 = {o[i][4] * inv, o[i][5] * inv, o[i][6] * inv, o[i][7] * inv};
        *(float4*)(orow + tx * 4) = w0;
        *(float4*)(orow + 64 + tx * 4) = w1;
    }
}

// ---------------------------------------------------------------------------
extern "C" void kernel_launch(void* const* d_in, const int* in_sizes, int n_in,
                              void* d_out, int out_size) {
    const float* x     = (const float*)d_in[0];
    const float* ck    = (const float*)d_in[1];
    const float* cv    = (const float*)d_in[2];
    const float* wqkv  = (const float*)d_in[3];
    const float* bqkv  = (const float*)d_in[4];
    const float* wproj = (const float*)d_in[5];
    const float* bproj = (const float*)d_in[6];
    float* out = (float*)d_out;

    // Split fp32 operands into bf16 hi/lo
    {
        int n4x = MM * HIDD / 4;
        int n4q = 3 * HIDD * HIDD / 4;
        int n4p = HIDD * HIDD / 4;
        k_split<0><<<(n4x + 255) / 256, 256>>>(x, n4x);
        k_split<1><<<(n4q + 255) / 256, 256>>>(wqkv, n4q);
        k_split<2><<<(n4p + 255) / 256, 256>>>(wproj, n4p);
    }

    const int smem_gemm = 3 * STG;   // 122880 bytes

    // K1: QKV projection (mma.sync) -> g_q/g_k/g_v  [B,H,S,D]
    cudaFuncSetAttribute(k_gemm_mma<1>, cudaFuncAttributeMaxDynamicSharedMemorySize,
                         smem_gemm);
    k_gemm_mma<1><<<dim3(3 * HIDD / 128, MM / 128), 256, smem_gemm>>>(bqkv, nullptr);

    // K2: flash attention -> g_attn  [B,S,H,D]
    const int smem_attn = (8192 + 8192 + 8192 + 64 * 68) * (int)sizeof(float);
    cudaFuncSetAttribute(k_attn, cudaFuncAttributeMaxDynamicSharedMemorySize,
                         smem_attn);
    k_attn<<<dim3(SS / 64, BB * HH), 256, smem_attn>>>(ck, cv);

    // Split attention output for K3
    {
        int n4a = MM * HIDD / 4;
        k_split<3><<<(n4a + 255) / 256, 256>>>(nullptr, n4a);
    }

    // K3: output projection (mma.sync) -> d_out
    cudaFuncSetAttribute(k_gemm_mma<0>, cudaFuncAttributeMaxDynamicSharedMemorySize,
                         smem_gemm);
    k_gemm_mma<0><<<dim3(HIDD / 128, MM / 128), 256, smem_gemm>>>(bproj, out);
}

// round 5
// speedup vs baseline: 2.7344x; 1.9739x over previous
#include <cuda_runtime.h>
#include <cuda_bf16.h>
#include <cstdint>

// Problem constants
#define BB    4
#define SS    1024
#define HIDD  2048
#define HH    16
#define DD    128
#define CACHE 2048
#define LTOT  (CACHE + SS)   // 3072
#define MM    (BB * SS)      // 4096

// ---------------------------------------------------------------------------
// Scratch (device globals: allocation-guard safe)
// ---------------------------------------------------------------------------
__device__ float g_q[MM * HIDD];     // [B,H,S,D]
__device__ float g_k[MM * HIDD];     // [B,H,S,D] (new K)
__device__ float g_v[MM * HIDD];     // [B,H,S,D] (new V)
__device__ float g_attn[MM * HIDD];  // [B,S,H,D] == [M, HID]

// bf16 hi/lo splits for tensor-core GEMMs
__device__ __align__(16) __nv_bfloat16 g_xh[MM * HIDD],        g_xl[MM * HIDD];
__device__ __align__(16) __nv_bfloat16 g_wqh[3 * HIDD * HIDD], g_wql[3 * HIDD * HIDD];
__device__ __align__(16) __nv_bfloat16 g_wph[HIDD * HIDD],     g_wpl[HIDD * HIDD];
__device__ __align__(16) __nv_bfloat16 g_ah[MM * HIDD],        g_al[MM * HIDD];

// ---------------------------------------------------------------------------
// Helpers (compute_103-safe: mma.sync / ldmatrix / cp.async only)
// ---------------------------------------------------------------------------
__device__ __forceinline__ uint32_t smem_u32(const void* p) {
    return (uint32_t)__cvta_generic_to_shared(p);
}

__device__ __forceinline__ void ldsm4(uint32_t* r, uint32_t addr) {
    asm volatile("ldmatrix.sync.aligned.m8n8.x4.shared.b16 {%0,%1,%2,%3}, [%4];"
                 : "=r"(r[0]), "=r"(r[1]), "=r"(r[2]), "=r"(r[3]) : "r"(addr));
}

__device__ __forceinline__ void ldsm4t(uint32_t* r, uint32_t addr) {
    asm volatile("ldmatrix.sync.aligned.m8n8.x4.trans.shared.b16 {%0,%1,%2,%3}, [%4];"
                 : "=r"(r[0]), "=r"(r[1]), "=r"(r[2]), "=r"(r[3]) : "r"(addr));
}

__device__ __forceinline__ void mma16816(float* c, const uint32_t* a,
                                         const uint32_t* b) {
    asm volatile(
        "mma.sync.aligned.m16n8k16.row.col.f32.bf16.bf16.f32 "
        "{%0,%1,%2,%3}, {%4,%5,%6,%7}, {%8,%9}, {%0,%1,%2,%3};"
        : "+f"(c[0]), "+f"(c[1]), "+f"(c[2]), "+f"(c[3])
        : "r"(a[0]), "r"(a[1]), "r"(a[2]), "r"(a[3]), "r"(b[0]), "r"(b[1]));
}

__device__ __forceinline__ void cp16(uint32_t dst, const void* src) {
    asm volatile("cp.async.cg.shared.global [%0], [%1], 16;"
                 :: "r"(dst), "l"(src) : "memory");
}
#define CP_COMMIT() asm volatile("cp.async.commit_group;" ::: "memory")
#define CP_WAIT1()  asm volatile("cp.async.wait_group 1;" ::: "memory")

// split float4 -> 4 bf16 hi (uint2) + 4 bf16 lo (uint2)
__device__ __forceinline__ void split4(float4 v, uint2& hi, uint2& lo) {
    __nv_bfloat162 h01 = __float22bfloat162_rn(make_float2(v.x, v.y));
    __nv_bfloat162 h23 = __float22bfloat162_rn(make_float2(v.z, v.w));
    float2 f01 = __bfloat1622float2(h01);
    float2 f23 = __bfloat1622float2(h23);
    __nv_bfloat162 l01 = __float22bfloat162_rn(make_float2(v.x - f01.x, v.y - f01.y));
    __nv_bfloat162 l23 = __float22bfloat162_rn(make_float2(v.z - f23.x, v.w - f23.y));
    hi.x = *(uint32_t*)&h01; hi.y = *(uint32_t*)&h23;
    lo.x = *(uint32_t*)&l01; lo.y = *(uint32_t*)&l23;
}

// split 2 floats -> packed bf16x2 hi + lo
__device__ __forceinline__ void split2(float x, float y, uint32_t& h, uint32_t& l) {
    __nv_bfloat162 hb = __float22bfloat162_rn(make_float2(x, y));
    float2 hf = __bfloat1622float2(hb);
    __nv_bfloat162 lb = __float22bfloat162_rn(make_float2(x - hf.x, y - hf.y));
    h = *(uint32_t*)&hb;
    l = *(uint32_t*)&lb;
}

// ---------------------------------------------------------------------------
// Fast exp on the FMA pipe.
// ---------------------------------------------------------------------------
__device__ __forceinline__ float fast_exp(float x) {
    float t = x * 1.4426950408889634f;
    t = fmaxf(t, -125.0f);
    float r = __fadd_rn(t, 12582912.0f);
    float f = __fsub_rn(t, __fsub_rn(r, 12582912.0f));
    float p = 1.3333558e-3f;
    p = fmaf(p, f, 9.6181291e-3f);
    p = fmaf(p, f, 5.5504109e-2f);
    p = fmaf(p, f, 2.4022651e-1f);
    p = fmaf(p, f, 6.9314718e-1f);
    p = fmaf(p, f, 1.0f);
    int n = __float_as_int(r) - 0x4B400000;
    return p * __int_as_float((n + 127) << 23);
}

// ---------------------------------------------------------------------------
// Split fp32 -> bf16 hi + bf16 lo (global prep for GEMMs)
// ---------------------------------------------------------------------------
template <int WHICH>
__global__ __launch_bounds__(256) void k_split(const float* __restrict__ in, int n4) {
    int i = blockIdx.x * 256 + threadIdx.x;
    if (i >= n4) return;
    const float4* src;
    uint2* dh;
    uint2* dl;
    if (WHICH == 0) { src = (const float4*)in;     dh = (uint2*)g_xh;  dl = (uint2*)g_xl; }
    if (WHICH == 1) { src = (const float4*)in;     dh = (uint2*)g_wqh; dl = (uint2*)g_wql; }
    if (WHICH == 2) { src = (const float4*)in;     dh = (uint2*)g_wph; dl = (uint2*)g_wpl; }
    if (WHICH == 3) { src = (const float4*)g_attn; dh = (uint2*)g_ah;  dl = (uint2*)g_al; }
    uint2 hi, lo;
    split4(src[i], hi, lo);
    dh[i] = hi;
    dl[i] = lo;
}

// ---------------------------------------------------------------------------
// mma.sync bf16 split-fp32 GEMM:  C[m,n] = sum_k A[m,k]*B[n,k] + bias[n]
// Tile 128x128, KC=32, 2-stage cp.async pipeline (80KB -> 2 CTA/SM), 8 warps.
// ---------------------------------------------------------------------------
#define TILEB  (128 * 80)          // 10240 bytes per bf16 tile
#define STG    (4 * TILEB)         // Ah, Al, Bh, Bl
#define NIT    (HIDD / 32)         // 64

template <int MODE>
__global__ __launch_bounds__(256) void k_gemm_mma(const float* __restrict__ bias,
                                                  float* __restrict__ out)
{
    extern __shared__ __align__(128) char smem[];   // 2 * STG

    const __nv_bfloat16* __restrict__ Ah = MODE ? g_xh : g_ah;
    const __nv_bfloat16* __restrict__ Al = MODE ? g_xl : g_al;
    const __nv_bfloat16* __restrict__ Bh = MODE ? g_wqh : g_wph;
    const __nv_bfloat16* __restrict__ Bl = MODE ? g_wql : g_wpl;

    const int tid = threadIdx.x;
    const int wid = tid >> 5, lane = tid & 31;
    const int m0 = blockIdx.y * 128;
    const int n0 = blockIdx.x * 128;
    const int warp_m = wid & 1;
    const int warp_n = wid >> 1;

    const int lr = tid >> 2;
    const int lc = tid & 3;
    const size_t aoff0 = (size_t)(m0 + lr) * HIDD + lc * 8;
    const size_t aoff1 = (size_t)(m0 + 64 + lr) * HIDD + lc * 8;
    const size_t boff0 = (size_t)(n0 + lr) * HIDD + lc * 8;
    const size_t boff1 = (size_t)(n0 + 64 + lr) * HIDD + lc * 8;
    const int dst0 = lr * 80 + lc * 16;
    const int dst1 = (64 + lr) * 80 + lc * 16;

    auto issue = [&](int t, int slot) {
        const int kc = t * 32;
        uint32_t s0 = smem_u32(smem + slot * STG);
        cp16(s0 + 0 * TILEB + dst0, Ah + aoff0 + kc);
        cp16(s0 + 0 * TILEB + dst1, Ah + aoff1 + kc);
        cp16(s0 + 1 * TILEB + dst0, Al + aoff0 + kc);
        cp16(s0 + 1 * TILEB + dst1, Al + aoff1 + kc);
        cp16(s0 + 2 * TILEB + dst0, Bh + boff0 + kc);
        cp16(s0 + 2 * TILEB + dst1, Bh + boff1 + kc);
        cp16(s0 + 3 * TILEB + dst0, Bl + boff0 + kc);
        cp16(s0 + 3 * TILEB + dst1, Bl + boff1 + kc);
        CP_COMMIT();
    };

    const int arow_l = lane & 15;
    const int ac16   = lane >> 4;
    const int brow_l = (lane & 7) + (lane >> 4) * 8;
    const int bc16   = (lane >> 3) & 1;

    float acc[4][4][4];
#pragma unroll
    for (int mf = 0; mf < 4; mf++)
#pragma unroll
        for (int nf = 0; nf < 4; nf++)
#pragma unroll
            for (int c = 0; c < 4; c++) acc[mf][nf][c] = 0.f;

    issue(0, 0);
    issue(1, 1);

    for (int t = 0; t < NIT; t++) {
        CP_WAIT1();
        __syncthreads();

        const uint32_t sb = smem_u32(smem + (t & 1) * STG);
        const uint32_t sAh = sb;
        const uint32_t sAl = sb + TILEB;
        const uint32_t sBh = sb + 2 * TILEB;
        const uint32_t sBl = sb + 3 * TILEB;

#pragma unroll
        for (int kk = 0; kk < 2; kk++) {
            uint32_t ah[4][4], al[4][4], bh[2][4], bl[2][4];
            const int acol = (kk * 2 + ac16) * 16;
            const int bcol = (kk * 2 + bc16) * 16;
#pragma unroll
            for (int mf = 0; mf < 4; mf++) {
                const int row = warp_m * 64 + mf * 16 + arow_l;
                ldsm4(ah[mf], sAh + row * 80 + acol);
                ldsm4(al[mf], sAl + row * 80 + acol);
            }
#pragma unroll
            for (int nf2 = 0; nf2 < 2; nf2++) {
                const int row = warp_n * 32 + nf2 * 16 + brow_l;
                ldsm4(bh[nf2], sBh + row * 80 + bcol);
                ldsm4(bl[nf2], sBl + row * 80 + bcol);
            }
#pragma unroll
            for (int mf = 0; mf < 4; mf++)
#pragma unroll
                for (int nf = 0; nf < 4; nf++) {
                    const uint32_t* bph = &bh[nf >> 1][(nf & 1) * 2];
                    const uint32_t* bpl = &bl[nf >> 1][(nf & 1) * 2];
                    mma16816(acc[mf][nf], ah[mf], bph);
                    mma16816(acc[mf][nf], ah[mf], bpl);
                    mma16816(acc[mf][nf], al[mf], bph);
                }
        }

        if (t + 2 < NIT) {
            __syncthreads();
            issue(t + 2, t & 1);
        }
    }

    // epilogue
#pragma unroll
    for (int mf = 0; mf < 4; mf++) {
#pragma unroll
        for (int nf = 0; nf < 4; nf++) {
            const int gm = m0 + warp_m * 64 + mf * 16 + (lane >> 2);
            const int dn = warp_n * 32 + nf * 8 + (lane & 3) * 2;
            const float b0 = __ldg(bias + n0 + dn);
            const float b1 = __ldg(bias + n0 + dn + 1);
            float* p0;
            if (MODE == 0) {
                p0 = out + (size_t)gm * HIDD + n0 + dn;
            } else {
                const int which = n0 >> 11;
                const int h = (n0 >> 7) & 15;
                float* base = (which == 0) ? g_q : ((which == 1) ? g_k : g_v);
                const int bb = gm >> 10, sq = gm & 1023;
                p0 = base + ((((size_t)bb * HH + h) << 10) + sq) * DD + dn;
            }
            float2 v0 = {acc[mf][nf][0] + b0, acc[mf][nf][1] + b1};
            *(float2*)p0 = v0;
            float* p1 = (MODE == 0) ? (p0 + 8 * HIDD) : (p0 + 8 * DD);
            float2 v1 = {acc[mf][nf][2] + b0, acc[mf][nf][3] + b1};
            *(float2*)p1 = v1;
        }
    }
}

// ---------------------------------------------------------------------------
// Flash attention on mma.sync, full hi/lo splitting (Q,K,P,V).
// BQ=128 (8 warps x 16 rows), BKV=64, D=128, 256 threads, 1 CTA/SM.
// smem: Qh,Ql[128][272B] Kh,Kl[64][272B] Vh,Vl[64][272B] = 136 KB.
// ---------------------------------------------------------------------------
#define QSTRIDE 272
#define A_QH 0
#define A_QL 34816
#define A_KH 69632
#define A_KL 87040
#define A_VH 104448
#define A_VL 121856
#define A_TOT 139264

__global__ __launch_bounds__(256) void k_attn_mma(
    const float* __restrict__ ck, const float* __restrict__ cv)
{
    extern __shared__ __align__(128) char sm[];
    const uint32_t sbase = smem_u32(sm);

    const int tid = threadIdx.x;
    const int wid = tid >> 5, lane = tid & 31;
    const int bh = blockIdx.y;
    const int b = bh >> 4, h = bh & 15;
    const int q0 = blockIdx.x * 128;
    const float scale = 0.08838834764831845f;   // 1/sqrt(128)

    // ---- load Q (scaled), split into Qh/Ql smem ----
    {
        const float* qbase = g_q + ((size_t)bh * SS + q0) * DD;
#pragma unroll
        for (int i = 0; i < 16; i++) {
            int idx = tid + i * 256;             // 0..4095 float4 slots
            int row = idx >> 5;
            int c4 = idx & 31;
            float4 v = *(const float4*)(qbase + row * DD + c4 * 4);
            v.x *= scale; v.y *= scale; v.z *= scale; v.w *= scale;
            uint2 hi, lo;
            split4(v, hi, lo);
            *(uint2*)(sm + A_QH + row * QSTRIDE + c4 * 8) = hi;
            *(uint2*)(sm + A_QL + row * QSTRIDE + c4 * 8) = lo;
        }
    }

    const float* knew = g_k + ((size_t)bh) * (SS * DD);
    const float* vnew = g_v + ((size_t)bh) * (SS * DD);

    // per-thread softmax state (rows lane/4 and lane/4+8 of warp's 16 rows)
    float m0 = -1e30f, m1 = -1e30f, l0 = 0.f, l1 = 0.f;
    float o[16][4];
#pragma unroll
    for (int nd = 0; nd < 16; nd++)
#pragma unroll
        for (int c = 0; c < 4; c++) o[nd][c] = 0.f;

    // frag address components
    const int arow = lane & 15;                  // A (Q / ldsm rows)
    const int ac16 = lane >> 4;
    const int brow = (lane & 7) + (lane >> 4) * 8;  // B (K, non-trans)
    const int bc16 = (lane >> 3) & 1;
    const uint32_t qah = sbase + A_QH + (wid * 16 + arow) * QSTRIDE + ac16 * 16;
    const uint32_t qal = sbase + A_QL + (wid * 16 + arow) * QSTRIDE + ac16 * 16;
    const uint32_t vrow_addr = (lane & 15) * QSTRIDE + (lane >> 4) * 16;

    for (int t = 0; t < LTOT / 64; t++) {
        const int kv0 = t * 64;
        __syncthreads();   // protect K/V smem from previous iteration readers

        // ---- load K,V fp32, split into smem ----
#pragma unroll
        for (int i = 0; i < 8; i++) {
            int idx = tid + i * 256;             // 0..2047 float4 slots
            int row = idx >> 5;
            int c4 = idx & 31;
            int kv = kv0 + row;
            const float* ksrc = (kv < CACHE)
                ? (ck + ((size_t)kv * HH + h) * DD)
                : (knew + (size_t)(kv - CACHE) * DD);
            uint2 hi, lo;
            split4(*(const float4*)(ksrc + c4 * 4), hi, lo);
            *(uint2*)(sm + A_KH + row * QSTRIDE + c4 * 8) = hi;
            *(uint2*)(sm + A_KL + row * QSTRIDE + c4 * 8) = lo;
        }
#pragma unroll
        for (int i = 0; i < 8; i++) {
            int idx = tid + i * 256;
            int row = idx >> 5;
            int c4 = idx & 31;
            int kv = kv0 + row;
            const float* vsrc = (kv < CACHE)
                ? (cv + ((size_t)kv * HH + h) * DD)
                : (vnew + (size_t)(kv - CACHE) * DD);
            uint2 hi, lo;
            split4(*(const float4*)(vsrc + c4 * 4), hi, lo);
            *(uint2*)(sm + A_VH + row * QSTRIDE + c4 * 8) = hi;
            *(uint2*)(sm + A_VL + row * QSTRIDE + c4 * 8) = lo;
        }
        __syncthreads();

        // ---- S = Q @ K^T  (split: qh*kh + qh*kl + ql*kh) ----
        float s[8][4];
#pragma unroll
        for (int nf = 0; nf < 8; nf++)
#pragma unroll
            for (int c = 0; c < 4; c++) s[nf][c] = 0.f;

#pragma unroll
        for (int ks = 0; ks < 8; ks++) {
            uint32_t qh[4], ql[4];
            ldsm4(qh, qah + ks * 32);
            ldsm4(ql, qal + ks * 32);
#pragma unroll
            for (int np = 0; np < 4; np++) {
                uint32_t kh[4], kl[4];
                const uint32_t ka = (np * 16 + brow) * QSTRIDE + bc16 * 16 + ks * 32;
                ldsm4(kh, sbase + A_KH + ka);
                ldsm4(kl, sbase + A_KL + ka);
#pragma unroll
                for (int j = 0; j < 2; j++) {
                    mma16816(s[np * 2 + j], qh, &kh[j * 2]);
                    mma16816(s[np * 2 + j], qh, &kl[j * 2]);
                    mma16816(s[np * 2 + j], ql, &kh[j * 2]);
                }
            }
        }

        // ---- online softmax on C fragments ----
        float mx0 = -1e30f, mx1 = -1e30f;
#pragma unroll
        for (int nf = 0; nf < 8; nf++) {
            mx0 = fmaxf(mx0, fmaxf(s[nf][0], s[nf][1]));
            mx1 = fmaxf(mx1, fmaxf(s[nf][2], s[nf][3]));
        }
        mx0 = fmaxf(mx0, __shfl_xor_sync(0xffffffffu, mx0, 1));
        mx0 = fmaxf(mx0, __shfl_xor_sync(0xffffffffu, mx0, 2));
        mx1 = fmaxf(mx1, __shfl_xor_sync(0xffffffffu, mx1, 1));
        mx1 = fmaxf(mx1, __shfl_xor_sync(0xffffffffu, mx1, 2));
        const float mn0 = fmaxf(m0, mx0);
        const float mn1 = fmaxf(m1, mx1);
        const float al0 = fast_exp(m0 - mn0);
        const float al1 = fast_exp(m1 - mn1);
        m0 = mn0; m1 = mn1;

        float sum0 = 0.f, sum1 = 0.f;
#pragma unroll
        for (int nf = 0; nf < 8; nf++) {
            s[nf][0] = fast_exp(s[nf][0] - mn0);
            s[nf][1] = fast_exp(s[nf][1] - mn0);
            s[nf][2] = fast_exp(s[nf][2] - mn1);
            s[nf][3] = fast_exp(s[nf][3] - mn1);
            sum0 += s[nf][0] + s[nf][1];
            sum1 += s[nf][2] + s[nf][3];
        }
        sum0 += __shfl_xor_sync(0xffffffffu, sum0, 1);
        sum0 += __shfl_xor_sync(0xffffffffu, sum0, 2);
        sum1 += __shfl_xor_sync(0xffffffffu, sum1, 1);
        sum1 += __shfl_xor_sync(0xffffffffu, sum1, 2);
        l0 = l0 * al0 + sum0;
        l1 = l1 * al1 + sum1;

#pragma unroll
        for (int nd = 0; nd < 16; nd++) {
            o[nd][0] *= al0; o[nd][1] *= al0;
            o[nd][2] *= al1; o[nd][3] *= al1;
        }

        // ---- pack P into A-fragments (hi/lo) ----
        uint32_t pah[4][4], pal[4][4];
#pragma unroll
        for (int np = 0; np < 4; np++) {
            split2(s[np * 2][0],     s[np * 2][1],     pah[np][0], pal[np][0]);
            split2(s[np * 2][2],     s[np * 2][3],     pah[np][1], pal[np][1]);
            split2(s[np * 2 + 1][0], s[np * 2 + 1][1], pah[np][2], pal[np][2]);
            split2(s[np * 2 + 1][2], s[np * 2 + 1][3], pah[np][3], pal[np][3]);
        }

        // ---- O += P @ V  (split: ph*vh + ph*vl + pl*vh) ----
#pragma unroll
        for (int ks = 0; ks < 4; ks++) {
#pragma unroll
            for (int nd2 = 0; nd2 < 8; nd2++) {
                uint32_t vh[4], vl[4];
                const uint32_t va = (ks * 16) * QSTRIDE + nd2 * 32 + vrow_addr;
                ldsm4t(vh, sbase + A_VH + va);
                ldsm4t(vl, sbase + A_VL + va);
#pragma unroll
                for (int j = 0; j < 2; j++) {
                    mma16816(o[nd2 * 2 + j], pah[ks], &vh[j * 2]);
                    mma16816(o[nd2 * 2 + j], pah[ks], &vl[j * 2]);
                    mma16816(o[nd2 * 2 + j], pal[ks], &vh[j * 2]);
                }
            }
        }
    }

    // ---- epilogue: normalize, write g_attn [B,S,H,D] ----
    const float inv0 = __fdividef(1.0f, l0);
    const float inv1 = __fdividef(1.0f, l1);
    const int r0 = q0 + wid * 16 + (lane >> 2);
    const int r1 = r0 + 8;
#pragma unroll
    for (int nd = 0; nd < 16; nd++) {
        const int d = nd * 8 + (lane & 3) * 2;
        float2 w0 = {o[nd][0] * inv0, o[nd][1] * inv0};
        float2 w1 = {o[nd][2] * inv1, o[nd][3] * inv1};
        *(float2*)(g_attn + ((size_t)b * SS + r0) * HIDD + h * DD + d) = w0;
        *(float2*)(g_attn + ((size_t)b * SS + r1) * HIDD + h * DD + d) = w1;
    }
}

// ---------------------------------------------------------------------------
extern "C" void kernel_launch(void* const* d_in, const int* in_sizes, int n_in,
                              void* d_out, int out_size) {
    const float* x     = (const float*)d_in[0];
    const float* ck    = (const float*)d_in[1];
    const float* cv    = (const float*)d_in[2];
    const float* wqkv  = (const float*)d_in[3];
    const float* bqkv  = (const float*)d_in[4];
    const float* wproj = (const float*)d_in[5];
    const float* bproj = (const float*)d_in[6];
    float* out = (float*)d_out;

    // Split fp32 operands into bf16 hi/lo
    {
        int n4x = MM * HIDD / 4;
        int n4q = 3 * HIDD * HIDD / 4;
        int n4p = HIDD * HIDD / 4;
        k_split<0><<<(n4x + 255) / 256, 256>>>(x, n4x);
        k_split<1><<<(n4q + 255) / 256, 256>>>(wqkv, n4q);
        k_split<2><<<(n4p + 255) / 256, 256>>>(wproj, n4p);
    }

    const int smem_gemm = 2 * STG;   // 81920 bytes -> 2 CTA/SM

    // K1: QKV projection (mma.sync) -> g_q/g_k/g_v  [B,H,S,D]
    cudaFuncSetAttribute(k_gemm_mma<1>, cudaFuncAttributeMaxDynamicSharedMemorySize,
                         smem_gemm);
    k_gemm_mma<1><<<dim3(3 * HIDD / 128, MM / 128), 256, smem_gemm>>>(bqkv, nullptr);

    // K2: flash attention (mma.sync) -> g_attn  [B,S,H,D]
    cudaFuncSetAttribute(k_attn_mma, cudaFuncAttributeMaxDynamicSharedMemorySize,
                         A_TOT);
    k_attn_mma<<<dim3(SS / 128, BB * HH), 256, A_TOT>>>(ck, cv);

    // Split attention output for K3
    {
        int n4a = MM * HIDD / 4;
        k_split<3><<<(n4a + 255) / 256, 256>>>(nullptr, n4a);
    }

    // K3: output projection (mma.sync) -> d_out
    cudaFuncSetAttribute(k_gemm_mma<0>, cudaFuncAttributeMaxDynamicSharedMemorySize,
                         smem_gemm);
    k_gemm_mma<0><<<dim3(HIDD / 128, MM / 128), 256, smem_gemm>>>(bproj, out);
}